// round 2
// baseline (speedup 1.0000x reference)
#include <cuda_runtime.h>
#include <cstdint>

#define B_ 16
#define N_ 2048
#define D_ 64
#define NROWS (B_ * N_)          // 32768
#define CAP 512
#define NITER 32
#define INVA 3.3333333f          // 1/(alpha-1), alpha=1.3

// Scratch: per-row sparse attention lists (+ fallback attn buffer if d_out
// doesn't carry the attn output). Static __device__ arrays — no allocation.
__device__ float          g_cval[(size_t)NROWS * CAP];
__device__ unsigned short g_cidx[(size_t)NROWS * CAP];
__device__ int            g_ccnt[NROWS];
__device__ float          g_attn_scratch[(size_t)NROWS * N_];

// ---------------------------------------------------------------------------
// K1: scores = Q K^T / sqrt(D).  64x64 output tile per block, 256 threads,
// each thread computes a 4x4 micro-tile. Tiles stored d-major in shared so the
// inner loop is two LDS.128 + 16 FFMA per d.
// ---------------------------------------------------------------------------
__global__ __launch_bounds__(256) void qk_kernel(
    const float* __restrict__ q, const float* __restrict__ k,
    float* __restrict__ scores)
{
    if (scores == nullptr) scores = g_attn_scratch;
    __shared__ __align__(16) float Qs[64][68];  // [d][row], pad 68 keeps 16B align
    __shared__ __align__(16) float Ks[64][68];  // [d][col]

    const int b  = blockIdx.z;
    const int n0 = blockIdx.y << 6;
    const int m0 = blockIdx.x << 6;
    const int tid = threadIdx.x;

    const float* qp = q + ((size_t)b * N_ + n0) * D_;
    const float* kp = k + ((size_t)b * N_ + m0) * D_;

    for (int l = tid; l < 64 * 16; l += 256) {
        int row = l >> 4;
        int c4  = (l & 15) << 2;
        float4 a = *(const float4*)(qp + row * D_ + c4);
        Qs[c4 + 0][row] = a.x; Qs[c4 + 1][row] = a.y;
        Qs[c4 + 2][row] = a.z; Qs[c4 + 3][row] = a.w;
        float4 c = *(const float4*)(kp + row * D_ + c4);
        Ks[c4 + 0][row] = c.x; Ks[c4 + 1][row] = c.y;
        Ks[c4 + 2][row] = c.z; Ks[c4 + 3][row] = c.w;
    }
    __syncthreads();

    const int tr = tid >> 4;   // 0..15 -> row group
    const int tc = tid & 15;   // 0..15 -> col group

    float acc[4][4];
#pragma unroll
    for (int i = 0; i < 4; i++)
#pragma unroll
        for (int j = 0; j < 4; j++) acc[i][j] = 0.0f;

#pragma unroll 16
    for (int d = 0; d < 64; d++) {
        float4 a  = *(const float4*)&Qs[d][tr << 2];
        float4 bb = *(const float4*)&Ks[d][tc << 2];
        float av[4] = {a.x, a.y, a.z, a.w};
        float bv[4] = {bb.x, bb.y, bb.z, bb.w};
#pragma unroll
        for (int i = 0; i < 4; i++)
#pragma unroll
            for (int j = 0; j < 4; j++) acc[i][j] += av[i] * bv[j];
    }

#pragma unroll
    for (int i = 0; i < 4; i++) {
        float4 o;
        o.x = acc[i][0] * 0.125f;
        o.y = acc[i][1] * 0.125f;
        o.z = acc[i][2] * 0.125f;
        o.w = acc[i][3] * 0.125f;
        *(float4*)(scores + ((size_t)(b * N_ + n0 + (tr << 2) + i)) * N_ +
                   m0 + (tc << 2)) = o;
    }
}

// ---------------------------------------------------------------------------
// K2: entmax (alpha=1.3) per row via bisection on the analytic bracket
// tau in [-1, -0.1]:
//   root tau* satisfies sum (x - tau)^(10/3) = 1 with max(x)=0, so
//   (-tau)^(10/3) <= 1          -> tau >= -1
//   2048 * 0.1^(10/3) < 1       -> sum(hi) < 1, so tau* <= -0.1
// Elements with x <= -1 can never carry mass. Warp per row: compact survivors
// (deterministic ballot order), bisect 32 iters over the compact list only.
// Fallback (count > CAP): dense bisection from global.
// ---------------------------------------------------------------------------
__global__ __launch_bounds__(256) void entmax_kernel(float* attn)
{
    if (attn == nullptr) attn = g_attn_scratch;
    const int wid  = threadIdx.x >> 5;
    const int lane = threadIdx.x & 31;
    const int row  = (blockIdx.x << 3) + wid;

    __shared__ float          cval[8][CAP];
    __shared__ unsigned short cidx[8][CAP];

    float* srow = attn + (size_t)row * N_;

    float mx = -3.402823466e38f;
    for (int i = lane; i < N_; i += 32) mx = fmaxf(mx, srow[i]);
#pragma unroll
    for (int o = 16; o; o >>= 1)
        mx = fmaxf(mx, __shfl_xor_sync(0xffffffffu, mx, o));

    int base = 0;
    for (int i = lane; i < N_; i += 32) {
        float x = srow[i] - mx;
        bool act = (x > -1.0f);
        unsigned m = __ballot_sync(0xffffffffu, act);
        if (act) {
            int p = base + __popc(m & ((1u << lane) - 1u));
            if (p < CAP) {
                cval[wid][p] = x;
                cidx[wid][p] = (unsigned short)i;
            }
        }
        base += __popc(m);
    }
    const int n_act = base;

    float lo = -1.0f, hi = -0.1f;

    if (n_act <= CAP) {
        for (int it = 0; it < NITER; it++) {
            float tau = 0.5f * (lo + hi);
            float s = 0.0f;
            for (int i = lane; i < n_act; i += 32) {
                float t = cval[wid][i] - tau;
                if (t > 0.0f) s += __powf(t, INVA);
            }
#pragma unroll
            for (int o = 16; o; o >>= 1)
                s += __shfl_xor_sync(0xffffffffu, s, o);
            if (s > 1.0f) lo = tau; else hi = tau;
        }
        float tau = 0.5f * (lo + hi);

        float s = 0.0f;
        for (int i = lane; i < n_act; i += 32) {
            float t = cval[wid][i] - tau;
            float p = (t > 0.0f) ? __powf(t, INVA) : 0.0f;
            cval[wid][i] = p;
            s += p;
        }
#pragma unroll
        for (int o = 16; o; o >>= 1)
            s += __shfl_xor_sync(0xffffffffu, s, o);
        float nrm = 1.0f / (s + 1e-12f);

        float4 z = make_float4(0.f, 0.f, 0.f, 0.f);
        float4* zr = (float4*)srow;
        for (int i = lane; i < N_ / 4; i += 32) zr[i] = z;
        __syncwarp();
        for (int i = lane; i < n_act; i += 32) {
            float pv = cval[wid][i] * nrm;
            int ix = cidx[wid][i];
            srow[ix] = pv;
            g_cval[(size_t)row * CAP + i] = pv;
            g_cidx[(size_t)row * CAP + i] = (unsigned short)ix;
        }
        if (lane == 0) g_ccnt[row] = n_act;
    } else {
        for (int it = 0; it < NITER; it++) {
            float tau = 0.5f * (lo + hi);
            float s = 0.0f;
            for (int i = lane; i < N_; i += 32) {
                float t = srow[i] - mx - tau;
                if (t > 0.0f) s += __powf(t, INVA);
            }
#pragma unroll
            for (int o = 16; o; o >>= 1)
                s += __shfl_xor_sync(0xffffffffu, s, o);
            if (s > 1.0f) lo = tau; else hi = tau;
        }
        float tau = 0.5f * (lo + hi);
        float s = 0.0f;
        for (int i = lane; i < N_; i += 32) {
            float t = srow[i] - mx - tau;
            if (t > 0.0f) s += __powf(t, INVA);
        }
#pragma unroll
        for (int o = 16; o; o >>= 1)
            s += __shfl_xor_sync(0xffffffffu, s, o);
        float nrm = 1.0f / (s + 1e-12f);
        for (int i = lane; i < N_; i += 32) {
            float t = srow[i] - mx - tau;
            srow[i] = (t > 0.0f) ? __powf(t, INVA) * nrm : 0.0f;
        }
        if (lane == 0) g_ccnt[row] = -1;
    }
}

// ---------------------------------------------------------------------------
// K3: out = attn @ V via the sparse per-row lists (~25 nnz of 2048).
// Warp per row; each lane owns 2 of the 64 output columns.
// ---------------------------------------------------------------------------
__global__ __launch_bounds__(256) void av_kernel(
    const float* __restrict__ v, const float* attn, float* __restrict__ out)
{
    if (attn == nullptr) attn = g_attn_scratch;
    const int wid  = threadIdx.x >> 5;
    const int lane = threadIdx.x & 31;
    const int row  = (blockIdx.x << 3) + wid;
    const int b    = row >> 11;
    const float* vb = v + (size_t)b * N_ * D_;

    float a0 = 0.0f, a1 = 0.0f;
    int cnt = g_ccnt[row];
    if (cnt >= 0) {
        const float* pv = g_cval + (size_t)row * CAP;
        const unsigned short* pi = g_cidx + (size_t)row * CAP;
        for (int i = 0; i < cnt; i++) {
            float p = pv[i];
            int m = pi[i];
            a0 += p * vb[m * D_ + lane];
            a1 += p * vb[m * D_ + lane + 32];
        }
    } else {
        const float* arow = attn + (size_t)row * N_;
        for (int m = 0; m < N_; m++) {
            float p = arow[m];
            if (p != 0.0f) {
                a0 += p * vb[m * D_ + lane];
                a1 += p * vb[m * D_ + lane + 32];
            }
        }
    }
    out[(size_t)row * D_ + lane]      = a0;
    out[(size_t)row * D_ + lane + 32] = a1;
}

// ---------------------------------------------------------------------------
extern "C" void kernel_launch(void* const* d_in, const int* in_sizes, int n_in,
                              void* d_out, int out_size)
{
    const float* q = (const float*)d_in[0];
    const float* k = (const float*)d_in[1];
    const float* v = (const float*)d_in[2];

    const size_t BND = (size_t)B_ * N_ * D_;   //  2,097,152
    const size_t BNN = (size_t)B_ * N_ * N_;   // 67,108,864
    const size_t osz = (size_t)out_size;

    float* outp  = nullptr;
    float* attnp = nullptr;   // nullptr -> kernels use g_attn_scratch
    if (osz >= BND + BNN) {
        outp  = (float*)d_out;
        attnp = (float*)d_out + (osz - BNN);
    } else if (osz >= BNN) {
        attnp = (float*)d_out + (osz - BNN);
    } else {
        outp = (float*)d_out;  // attn staged in scratch only
    }

    dim3 g1(N_ / 64, N_ / 64, B_);
    qk_kernel<<<g1, 256>>>(q, k, attnp);       // raw scores into attn buffer
    entmax_kernel<<<NROWS / 8, 256>>>(attnp);  // in-place entmax + sparse lists
    if (outp)
        av_kernel<<<NROWS / 8, 256>>>(v, attnp, outp);
}

// round 3
// speedup vs baseline: 1.0152x; 1.0152x over previous
#include <cuda_runtime.h>
#include <cstdint>

#define B_ 16
#define N_ 2048
#define D_ 64
#define NROWS (B_ * N_)          // 32768
#define CAP 512
#define NITER 32
#define INVA 3.3333333f          // 1/(alpha-1), alpha=1.3

#define BR 128                   // rows per block (K1)
#define BC 128                   // cols per tile  (K1)
#define SP 132                   // padded smem row stride (floats)

// Scratch (static device arrays — no allocation).
__device__ float          g_cval[(size_t)NROWS * CAP];
__device__ unsigned short g_cidx[(size_t)NROWS * CAP];
__device__ int            g_ccnt[NROWS];
__device__ float          g_rowmax[NROWS];
__device__ float          g_attn_scratch[(size_t)NROWS * N_];

// ---------------------------------------------------------------------------
// K1 (fused): per block = 128 rows x all 2048 cols.
//   - Q tile (128x64, pre-scaled by 1/8) loaded once into smem, d-major.
//   - loop over 16 col tiles of 128: K tile to smem, 128x128x64 GEMM with
//     8x8 register microtiles (256 threads), then an in-register scan that
//     maintains per-row running max and appends candidates with
//     score > runmax - 1 to global sparse lists (deterministic ballot order).
//   Candidates are a superset of the final entmax support because
//   tau* >= -1 (proof: (-tau*)^(10/3) <= sum p = 1), so extras contribute 0.
// ---------------------------------------------------------------------------
__global__ __launch_bounds__(256, 2) void qk_fused_kernel(
    const float* __restrict__ q, const float* __restrict__ k)
{
    extern __shared__ float smem[];
    float* sQ = smem;            // [64][SP]
    float* sK = smem + 64 * SP;  // [64][SP]

    const int tid  = threadIdx.x;
    const int lane = tid & 31;
    const int w    = tid >> 5;          // warp 0..7
    const int u    = tid >> 4;          // row group 0..15
    const int c    = tid & 15;          // col group 0..15

    const int b   = blockIdx.y;
    const int r0  = blockIdx.x * BR;
    const int grow0 = b * N_ + r0;

    const float* qp = q + ((size_t)(b * N_ + r0)) * D_;
    const float* kb = k + ((size_t)b * N_) * D_;

    // ---- load Q tile (transpose to d-major, scale by 1/8) ----
    {
        int row   = tid >> 1;           // 0..127
        int dbase = (tid & 1) * 32;
#pragma unroll
        for (int t = 0; t < 8; t++) {
            int d0 = dbase + 4 * t;
            float4 a = *(const float4*)(qp + row * D_ + d0);
            sQ[(d0 + 0) * SP + row] = a.x * 0.125f;
            sQ[(d0 + 1) * SP + row] = a.y * 0.125f;
            sQ[(d0 + 2) * SP + row] = a.z * 0.125f;
            sQ[(d0 + 3) * SP + row] = a.w * 0.125f;
        }
    }

    // per-warp register state: this warp exclusively owns 16 rows.
    // lane<16: rows r(u=2w, i); lane>=16: rows r(u=2w+1, i), i=0..7.
    float rm[8];
    int   cnt8[8];
#pragma unroll
    for (int i = 0; i < 8; i++) { rm[i] = -3.402823466e38f; cnt8[i] = 0; }

    for (int ct = 0; ct < N_ / BC; ct++) {
        const int m0 = ct * BC;
        __syncthreads();   // everyone done reading previous sK
        // ---- load K tile ----
        {
            int row   = tid >> 1;
            int dbase = (tid & 1) * 32;
            const float* kp = kb + (size_t)(m0 + row) * D_;
#pragma unroll
            for (int t = 0; t < 8; t++) {
                int d0 = dbase + 4 * t;
                float4 a = *(const float4*)(kp + d0);
                sK[(d0 + 0) * SP + row] = a.x;
                sK[(d0 + 1) * SP + row] = a.y;
                sK[(d0 + 2) * SP + row] = a.z;
                sK[(d0 + 3) * SP + row] = a.w;
            }
        }
        __syncthreads();

        // ---- 128x128x64 GEMM, 8x8 per thread ----
        float acc[8][8];
#pragma unroll
        for (int i = 0; i < 8; i++)
#pragma unroll
            for (int j = 0; j < 8; j++) acc[i][j] = 0.0f;

#pragma unroll 8
        for (int d = 0; d < 64; d++) {
            float4 a0 = *(const float4*)&sQ[d * SP + 4 * u];
            float4 a1 = *(const float4*)&sQ[d * SP + 64 + 4 * u];
            float4 b0 = *(const float4*)&sK[d * SP + 4 * c];
            float4 b1 = *(const float4*)&sK[d * SP + 64 + 4 * c];
            float av[8] = {a0.x, a0.y, a0.z, a0.w, a1.x, a1.y, a1.z, a1.w};
            float bv[8] = {b0.x, b0.y, b0.z, b0.w, b1.x, b1.y, b1.z, b1.w};
#pragma unroll
            for (int i = 0; i < 8; i++)
#pragma unroll
                for (int j = 0; j < 8; j++) acc[i][j] += av[i] * bv[j];
        }

        // ---- scan: running max + candidate append (registers + shuffles) ----
#pragma unroll
        for (int i = 0; i < 8; i++) {
            int lrow = (i < 4) ? (4 * u + i) : (64 + 4 * u + i - 4);
            // row-tile max over this thread's 8 cols
            float m = acc[i][0];
#pragma unroll
            for (int j = 1; j < 8; j++) m = fmaxf(m, acc[i][j]);
            // half-warp (16-lane) reduce — xor offsets < 16 stay in half
            m = fmaxf(m, __shfl_xor_sync(0xffffffffu, m, 8));
            m = fmaxf(m, __shfl_xor_sync(0xffffffffu, m, 4));
            m = fmaxf(m, __shfl_xor_sync(0xffffffffu, m, 2));
            m = fmaxf(m, __shfl_xor_sync(0xffffffffu, m, 1));
            rm[i] = fmaxf(rm[i], m);
            const float thr = rm[i] - 1.0f;
            const size_t gbase = (size_t)(grow0 + lrow) * CAP;
#pragma unroll
            for (int j = 0; j < 8; j++) {
                float v = acc[i][j];
                bool p = (v > thr);
                unsigned bal  = __ballot_sync(0xffffffffu, p);
                unsigned half = (lane < 16) ? (bal & 0xFFFFu) : (bal >> 16);
                if (p) {
                    int pos = cnt8[i] + __popc(half & ((1u << (lane & 15)) - 1u));
                    if (pos < CAP) {
                        int col = m0 + ((j < 4) ? (4 * c + j)
                                                : (64 + 4 * c + j - 4));
                        g_cval[gbase + pos] = v;
                        g_cidx[gbase + pos] = (unsigned short)col;
                    }
                }
                cnt8[i] += __popc(half);
            }
        }
    }

    // ---- write per-row count and max ----
    if ((lane & 15) == 0) {
#pragma unroll
        for (int i = 0; i < 8; i++) {
            int lrow = (i < 4) ? (4 * u + i) : (64 + 4 * u + i - 4);
            g_ccnt[grow0 + lrow]   = cnt8[i];
            g_rowmax[grow0 + lrow] = rm[i];
        }
    }
}

// ---------------------------------------------------------------------------
// K2: per-row bisection over the candidate list (tau in [-1, -0.1]), then
// zero-fill + scatter the dense attn row, and rewrite g_cval with normalized
// probabilities for K3. Warp per row. Fallback (cnt > CAP, statistically
// never): recompute the row's scores densely from q,k.
// ---------------------------------------------------------------------------
__global__ __launch_bounds__(256) void entmax_kernel(
    const float* __restrict__ q, const float* __restrict__ k, float* attn)
{
    if (attn == nullptr) attn = g_attn_scratch;
    const int wid  = threadIdx.x >> 5;
    const int lane = threadIdx.x & 31;
    const int row  = (blockIdx.x << 3) + wid;
    float* srow = attn + (size_t)row * N_;

    const int   cnt = g_ccnt[row];
    const float mx  = g_rowmax[row];

    if (cnt <= CAP) {
        const size_t gbase = (size_t)row * CAP;
        const int nt = (cnt > lane) ? ((cnt - lane + 31) >> 5) : 0;
        float xv[16];
        for (int t = 0; t < nt; t++)
            xv[t] = g_cval[gbase + lane + 32 * t] - mx;

        float lo = -1.0f, hi = -0.1f;
        for (int it = 0; it < NITER; it++) {
            float tau = 0.5f * (lo + hi);
            float s = 0.0f;
            for (int t = 0; t < nt; t++) {
                float tt = xv[t] - tau;
                if (tt > 0.0f) s += __powf(tt, INVA);
            }
#pragma unroll
            for (int o = 16; o; o >>= 1)
                s += __shfl_xor_sync(0xffffffffu, s, o);
            if (s > 1.0f) lo = tau; else hi = tau;
        }
        float tau = 0.5f * (lo + hi);
        float s = 0.0f;
        for (int t = 0; t < nt; t++) {
            float tt = xv[t] - tau;
            float p = (tt > 0.0f) ? __powf(tt, INVA) : 0.0f;
            xv[t] = p;
            s += p;
        }
#pragma unroll
        for (int o = 16; o; o >>= 1)
            s += __shfl_xor_sync(0xffffffffu, s, o);
        float nrm = 1.0f / (s + 1e-12f);

        // zero-fill dense row, then scatter
        float4 z = make_float4(0.f, 0.f, 0.f, 0.f);
        float4* zr = (float4*)srow;
#pragma unroll
        for (int i = lane; i < N_ / 4; i += 32) zr[i] = z;
        __syncwarp();
        for (int t = 0; t < nt; t++) {
            float pv = xv[t] * nrm;
            int ii = lane + 32 * t;
            srow[g_cidx[gbase + ii]] = pv;
            g_cval[gbase + ii] = pv;   // normalized p for K3
        }
    } else {
        // dense fallback: recompute scores for this row
        const int b = row >> 11;
        const float* qr = q + (size_t)row * D_;
        const float* kb = k + (size_t)(b * N_) * D_;
        float sc[64];
        float qreg[64];
#pragma unroll
        for (int d = 0; d < 64; d++) qreg[d] = qr[d] * 0.125f;
        for (int t = 0; t < 64; t++) {
            const float* kp = kb + (size_t)(lane + 32 * t) * D_;
            float s = 0.0f;
#pragma unroll
            for (int d = 0; d < 64; d++) s += qreg[d] * kp[d];
            sc[t] = s;
        }
        float m2 = -3.402823466e38f;
        for (int t = 0; t < 64; t++) m2 = fmaxf(m2, sc[t]);
#pragma unroll
        for (int o = 16; o; o >>= 1)
            m2 = fmaxf(m2, __shfl_xor_sync(0xffffffffu, m2, o));

        float lo = -1.0f, hi = -0.1f;
        for (int it = 0; it < NITER; it++) {
            float tau = 0.5f * (lo + hi);
            float s = 0.0f;
            for (int t = 0; t < 64; t++) {
                float tt = sc[t] - m2 - tau;
                if (tt > 0.0f) s += __powf(tt, INVA);
            }
#pragma unroll
            for (int o = 16; o; o >>= 1)
                s += __shfl_xor_sync(0xffffffffu, s, o);
            if (s > 1.0f) lo = tau; else hi = tau;
        }
        float tau = 0.5f * (lo + hi);
        float s = 0.0f;
        for (int t = 0; t < 64; t++) {
            float tt = sc[t] - m2 - tau;
            float p = (tt > 0.0f) ? __powf(tt, INVA) : 0.0f;
            sc[t] = p;
            s += p;
        }
#pragma unroll
        for (int o = 16; o; o >>= 1)
            s += __shfl_xor_sync(0xffffffffu, s, o);
        float nrm = 1.0f / (s + 1e-12f);
        for (int t = 0; t < 64; t++)
            srow[lane + 32 * t] = sc[t] * nrm;
    }
}

// ---------------------------------------------------------------------------
// K3: out = attn @ V via the sparse per-row lists (zeros in the list are
// harmless). Warp per row; each lane owns 2 of the 64 output columns.
// ---------------------------------------------------------------------------
__global__ __launch_bounds__(256) void av_kernel(
    const float* __restrict__ v, const float* attn, float* __restrict__ out)
{
    if (attn == nullptr) attn = g_attn_scratch;
    const int wid  = threadIdx.x >> 5;
    const int lane = threadIdx.x & 31;
    const int row  = (blockIdx.x << 3) + wid;
    const int b    = row >> 11;
    const float* vb = v + (size_t)b * N_ * D_;

    float a0 = 0.0f, a1 = 0.0f;
    int cnt = g_ccnt[row];
    if (cnt <= CAP) {
        const float* pv = g_cval + (size_t)row * CAP;
        const unsigned short* pi = g_cidx + (size_t)row * CAP;
        for (int i = 0; i < cnt; i++) {
            float p = pv[i];
            int m = pi[i];
            a0 += p * vb[m * D_ + lane];
            a1 += p * vb[m * D_ + lane + 32];
        }
    } else {
        const float* arow = attn + (size_t)row * N_;
        for (int m = 0; m < N_; m++) {
            float p = arow[m];
            if (p != 0.0f) {
                a0 += p * vb[m * D_ + lane];
                a1 += p * vb[m * D_ + lane + 32];
            }
        }
    }
    out[(size_t)row * D_ + lane]      = a0;
    out[(size_t)row * D_ + lane + 32] = a1;
}

// ---------------------------------------------------------------------------
extern "C" void kernel_launch(void* const* d_in, const int* in_sizes, int n_in,
                              void* d_out, int out_size)
{
    const float* q = (const float*)d_in[0];
    const float* k = (const float*)d_in[1];
    const float* v = (const float*)d_in[2];

    const size_t BND = (size_t)B_ * N_ * D_;   //  2,097,152
    const size_t BNN = (size_t)B_ * N_ * N_;   // 67,108,864
    const size_t osz = (size_t)out_size;

    float* outp  = nullptr;
    float* attnp = nullptr;   // nullptr -> kernels use g_attn_scratch
    if (osz >= BND + BNN) {
        outp  = (float*)d_out;
        attnp = (float*)d_out + (osz - BNN);
    } else if (osz >= BNN) {
        attnp = (float*)d_out + (osz - BNN);
    } else {
        outp = (float*)d_out;
    }

    const int smem_bytes = 2 * 64 * SP * sizeof(float);  // 67584
    cudaFuncSetAttribute(qk_fused_kernel,
                         cudaFuncAttributeMaxDynamicSharedMemorySize,
                         smem_bytes);

    dim3 g1(N_ / BR, B_);
    qk_fused_kernel<<<g1, 256, smem_bytes>>>(q, k);
    entmax_kernel<<<NROWS / 8, 256>>>(q, k, attnp);
    if (outp)
        av_kernel<<<NROWS / 8, 256>>>(v, attnp, outp);
}